// round 3
// baseline (speedup 1.0000x reference)
#include <cuda_runtime.h>

#define B_ 128
#define H_ 40
#define W_ 40
#define C_ 16
#define NPIX_ (B_*H_*W_)   /* 204800 */

/* Scratch (no allocations allowed): ping-pong state + pre-mask buffer. */
__device__ float g_state_buf[2][(size_t)NPIX_*C_];
__device__ float g_pre_buf[(size_t)NPIX_*C_];

typedef unsigned long long u64;

static __device__ __forceinline__ u64 pk2(float x){u64 r;asm("mov.b64 %0,{%1,%1};":"=l"(r):"f"(x));return r;}
static __device__ __forceinline__ u64 pkab(float a,float b){u64 r;asm("mov.b64 %0,{%1,%2};":"=l"(r):"f"(a),"f"(b));return r;}
static __device__ __forceinline__ void upk(u64 v,float&a,float&b){float x,y;asm("mov.b64 {%0,%1},%2;":"=f"(x),"=f"(y):"l"(v));a=x;b=y;}
static __device__ __forceinline__ u64 ffma2(u64 a,u64 b,u64 c){u64 d;asm("fma.rn.f32x2 %0,%1,%2,%3;":"=l"(d):"l"(a),"l"(b),"l"(c));return d;}
static __device__ __forceinline__ u64 fadd2(u64 a,u64 b){u64 d;asm("add.rn.f32x2 %0,%1,%2;":"=l"(d):"l"(a),"l"(b));return d;}

/* One perception component: accumulate 32 hidden (16 f32x2) for 2 pixels. */
static __device__ __forceinline__ void pass16(const float* wbase,float v0,float v1,u64* a0,u64* a1){
  u64 pd0=pk2(v0), pd1=pk2(v1);
  const ulonglong2* wp=(const ulonglong2*)wbase;
#pragma unroll
  for(int q=0;q<8;q++){
    ulonglong2 w=wp[q];
    a0[2*q]  =ffma2(w.x,pd0,a0[2*q]);
    a0[2*q+1]=ffma2(w.y,pd0,a0[2*q+1]);
    a1[2*q]  =ffma2(w.x,pd1,a1[2*q]);
    a1[2*q+1]=ffma2(w.y,pd1,a1[2*q+1]);
  }
}

/* One hidden unit: accumulate 16 outputs (8 f32x2) for 2 pixels. */
static __device__ __forceinline__ void g2pass(const float* w,float h0,float h1,u64* u0,u64* u1){
  const ulonglong2* wp=(const ulonglong2*)w;
  ulonglong2 wA=wp[0],wB=wp[1],wC=wp[2],wD=wp[3];
  u64 hd0=pk2(h0), hd1=pk2(h1);
  u0[0]=ffma2(wA.x,hd0,u0[0]); u0[1]=ffma2(wA.y,hd0,u0[1]);
  u0[2]=ffma2(wB.x,hd0,u0[2]); u0[3]=ffma2(wB.y,hd0,u0[3]);
  u0[4]=ffma2(wC.x,hd0,u0[4]); u0[5]=ffma2(wC.y,hd0,u0[5]);
  u0[6]=ffma2(wD.x,hd0,u0[6]); u0[7]=ffma2(wD.y,hd0,u0[7]);
  u1[0]=ffma2(wA.x,hd1,u1[0]); u1[1]=ffma2(wA.y,hd1,u1[1]);
  u1[2]=ffma2(wB.x,hd1,u1[2]); u1[3]=ffma2(wB.y,hd1,u1[3]);
  u1[4]=ffma2(wC.x,hd1,u1[4]); u1[5]=ffma2(wC.y,hd1,u1[5]);
  u1[6]=ffma2(wD.x,hd1,u1[6]); u1[7]=ffma2(wD.y,hd1,u1[7]);
}

/* stacked frame + rgb writer for one pixel */
static __device__ __forceinline__ void write_frame(int f,int pix,const float4* v,
    float* stkF,float* rgbF,unsigned char* rgbU){
  size_t base=(size_t)f*NPIX_+pix;
  if(stkF){ float4* d=(float4*)(stkF+base*C_); d[0]=v[0];d[1]=v[1];d[2]=v[2];d[3]=v[3]; }
  if(rgbU||rgbF){
    float a=fminf(fmaxf(v[0].w,0.f),1.f);
    unsigned char r=(unsigned char)(fminf(fmaxf(1.f-a+v[0].x,0.f),1.f)*255.f);
    unsigned char g=(unsigned char)(fminf(fmaxf(1.f-a+v[0].y,0.f),1.f)*255.f);
    unsigned char b=(unsigned char)(fminf(fmaxf(1.f-a+v[0].z,0.f),1.f)*255.f);
    if(rgbU){ rgbU[base*3+0]=r; rgbU[base*3+1]=g; rgbU[base*3+2]=b; }
    if(rgbF){ rgbF[base*3+0]=(float)r; rgbF[base*3+1]=(float)g; rgbF[base*3+2]=(float)b; }
  }
}

/* ---- init: state[0] = input; emit frame 0 ---- */
__global__ void k_init(const float* __restrict__ st0,
                       float* stkF,float* rgbF,unsigned char* rgbU){
  int pix=blockIdx.x*blockDim.x+threadIdx.x;
  if(pix>=NPIX_) return;
  float4 v[4];
  const float4* s=(const float4*)(st0+(size_t)pix*C_);
  v[0]=s[0];v[1]=s[1];v[2]=s[2];v[3]=s[3];
  float4* d=(float4*)(g_state_buf[0]+(size_t)pix*C_);
  d[0]=v[0];d[1]=v[1];d[2]=v[2];d[3]=v[3];
  write_frame(0,pix,v,stkF,rgbF,rgbU);
}

/* ---- K1: pre = state + mask*MLP(perception(alive-masked state)) ----
 * grid (5,5,128) of 8x8 tiles; 128 thr = 32 pixel-pairs x 4 hidden-groups. */
__global__ void __launch_bounds__(128) k_pre(int sel,
    const float* __restrict__ W1,const float* __restrict__ b1,
    const float* __restrict__ W2,const int* __restrict__ umask)
{
  __shared__ __align__(16) float sW1[48*4*36];   /* [i][jg][32+4pad] */
  __shared__ __align__(16) float sW2[32*4*20];   /* [jj][jg][16+4pad] */
  __shared__ float sb1[128];
  __shared__ float sAl[12*12];
  __shared__ float sAm[100];
  __shared__ __align__(16) float sM[C_*10*12];   /* masked, [c][y][x pad12] */

  const int tid=threadIdx.x;
  const int b=blockIdx.z, by0=blockIdx.y*8, bx0=blockIdx.x*8;
  const float* __restrict__ sb=g_state_buf[sel]+(size_t)b*H_*W_*C_;

  /* alpha with halo 2 (OOB = -inf) */
  for(int idx=tid; idx<144; idx+=128){
    int ay=idx/12, ax=idx-ay*12;
    int gy=by0-2+ay, gx=bx0-2+ax;
    float a=-1e30f;
    if((unsigned)gy<(unsigned)H_ && (unsigned)gx<(unsigned)W_) a=sb[(gy*W_+gx)*C_+3];
    sAl[idx]=a;
  }
  /* stage weights in banked layouts */
  for(int idx=tid; idx<48*128; idx+=128){
    int j=idx/48, i=idx-j*48;
    sW1[(i*4+(j>>5))*36 + (j&31)] = W1[idx];
  }
  for(int idx=tid; idx<16*128; idx+=128){
    int o=idx>>7, j=idx&127;
    sW2[((j&31)*4 + (j>>5))*20 + o] = W2[idx];
  }
  sb1[tid]=b1[tid];
  __syncthreads();

  /* alive mask on 10x10 (halo 1) */
  for(int idx=tid; idx<100; idx+=128){
    int my=idx/10, mx=idx-my*10;
    const float* a0=&sAl[my*12+mx];
    float m=a0[0]; m=fmaxf(m,a0[1]); m=fmaxf(m,a0[2]);
    m=fmaxf(m,a0[12]); m=fmaxf(m,a0[13]); m=fmaxf(m,a0[14]);
    m=fmaxf(m,a0[24]); m=fmaxf(m,a0[25]); m=fmaxf(m,a0[26]);
    sAm[idx]=(m>=0.1f)?1.0f:0.0f;
  }
  __syncthreads();

  /* masked = state*am on 10x10, channel-major */
  for(int idx=tid; idx<400; idx+=128){
    int p=idx>>2, c4=idx&3;
    int my=p/10, mx=p-my*10;
    int gy=by0-1+my, gx=bx0-1+mx;
    float4 v=make_float4(0.f,0.f,0.f,0.f);
    if((unsigned)gy<(unsigned)H_ && (unsigned)gx<(unsigned)W_)
      v=*(const float4*)&sb[(gy*W_+gx)*C_ + c4*4];
    float am=sAm[p];
    int c0=c4*4;
    sM[((c0  )*10+my)*12+mx]=v.x*am;
    sM[((c0+1)*10+my)*12+mx]=v.y*am;
    sM[((c0+2)*10+my)*12+mx]=v.z*am;
    sM[((c0+3)*10+my)*12+mx]=v.w*am;
  }
  __syncthreads();

  const int jg=tid&3, pp=tid>>2;
  const int ty=pp>>2, tx0=(pp&3)*2;

  u64 acc0[16], acc1[16];
#pragma unroll
  for(int a=0;a<16;a++){
    u64 bb=pkab(sb1[jg*32+2*a], sb1[jg*32+2*a+1]);
    acc0[a]=bb; acc1[a]=bb;
  }

  /* GEMM1 fused with perception (identity / sobel-x / sobel-y per channel) */
#pragma unroll 2
  for(int c=0;c<16;c++){
    const float* mrow=&sM[(c*10+ty)*12 + tx0];
    float2 r00=*(const float2*)(mrow);    float2 r01=*(const float2*)(mrow+2);
    float2 r10=*(const float2*)(mrow+12); float2 r11=*(const float2*)(mrow+14);
    float2 r20=*(const float2*)(mrow+24); float2 r21=*(const float2*)(mrow+26);
    float id0=r10.y, id1=r11.x;
    float cs0=r00.x+2.f*r10.x+r20.x;
    float cs1=r00.y+2.f*r10.y+r20.y;
    float cs2=r01.x+2.f*r11.x+r21.x;
    float cs3=r01.y+2.f*r11.y+r21.y;
    float sx0=(cs2-cs0)*0.125f, sx1=(cs3-cs1)*0.125f;
    float sy0=((r20.x+2.f*r20.y+r21.x)-(r00.x+2.f*r00.y+r01.x))*0.125f;
    float sy1=((r20.y+2.f*r21.x+r21.y)-(r00.y+2.f*r01.x+r01.y))*0.125f;
    pass16(&sW1[(( 0+c)*4+jg)*36], id0, id1, acc0, acc1);
    pass16(&sW1[((16+c)*4+jg)*36], sx0, sx1, acc0, acc1);
    pass16(&sW1[((32+c)*4+jg)*36], sy0, sy1, acc0, acc1);
  }

  /* ReLU + GEMM2 (partial over this thread's 32 hidden units) */
  u64 u0[8], u1[8];
#pragma unroll
  for(int k=0;k<8;k++){u0[k]=0ull; u1[k]=0ull;}
#pragma unroll
  for(int a=0;a<16;a++){
    float h0l,h0h,h1l,h1h;
    upk(acc0[a],h0l,h0h); upk(acc1[a],h1l,h1h);
    h0l=fmaxf(h0l,0.f); h0h=fmaxf(h0h,0.f);
    h1l=fmaxf(h1l,0.f); h1h=fmaxf(h1h,0.f);
    g2pass(&sW2[((2*a  )*4+jg)*20], h0l, h1l, u0, u1);
    g2pass(&sW2[((2*a+1)*4+jg)*20], h0h, h1h, u0, u1);
  }

  /* reduce over 4 hidden-groups (lane bits 0..1) */
#pragma unroll
  for(int k=0;k<8;k++){
    u0[k]=fadd2(u0[k], __shfl_xor_sync(0xffffffffu,u0[k],1));
    u0[k]=fadd2(u0[k], __shfl_xor_sync(0xffffffffu,u0[k],2));
    u1[k]=fadd2(u1[k], __shfl_xor_sync(0xffffffffu,u1[k],1));
    u1[k]=fadd2(u1[k], __shfl_xor_sync(0xffffffffu,u1[k],2));
  }

  if(jg==0){
    int gy=by0+ty, gx0=bx0+tx0;
    float m0=(float)umask[(b*H_+gy)*W_+gx0];
    float m1=(float)umask[(b*H_+gy)*W_+gx0+1];
    float o0[16], o1[16];
#pragma unroll
    for(int k=0;k<8;k++){ upk(u0[k],o0[2*k],o0[2*k+1]); upk(u1[k],o1[2*k],o1[2*k+1]); }
    size_t p0=((size_t)(b*H_+gy)*W_+gx0)*C_;
    const float4* s0=(const float4*)&sb[(gy*W_+gx0)*C_];
    const float4* s1=(const float4*)&sb[(gy*W_+gx0+1)*C_];
    float4* d0=(float4*)(g_pre_buf+p0);
    float4* d1=(float4*)(g_pre_buf+p0+C_);
#pragma unroll
    for(int c4=0;c4<4;c4++){
      float4 a=s0[c4], bq=s1[c4];
      float4 w;
      w.x=a.x+m0*o0[4*c4+0]; w.y=a.y+m0*o0[4*c4+1];
      w.z=a.z+m0*o0[4*c4+2]; w.w=a.w+m0*o0[4*c4+3];
      d0[c4]=w;
      w.x=bq.x+m1*o1[4*c4+0]; w.y=bq.y+m1*o1[4*c4+1];
      w.z=bq.z+m1*o1[4*c4+2]; w.w=bq.w+m1*o1[4*c4+3];
      d1[c4]=w;
    }
  }
}

/* ---- K2: new = pre * alive_mask(pre); store state + frame ---- */
__global__ void k_post(int nsel,int f,float* stkF,float* rgbF,unsigned char* rgbU){
  int pix=blockIdx.x*blockDim.x+threadIdx.x;
  if(pix>=NPIX_) return;
  int b=pix/(H_*W_); int rem=pix-b*(H_*W_); int y=rem/W_; int x=rem-y*W_;
  float m=-1e30f;
#pragma unroll
  for(int dy=-1;dy<=1;dy++){
    int yy=y+dy; if((unsigned)yy>=(unsigned)H_) continue;
#pragma unroll
    for(int dx=-1;dx<=1;dx++){
      int xx=x+dx; if((unsigned)xx>=(unsigned)W_) continue;
      m=fmaxf(m, g_pre_buf[((size_t)(b*H_+yy)*W_+xx)*C_+3]);
    }
  }
  float am=(m>=0.1f)?1.0f:0.0f;
  const float4* s=(const float4*)(g_pre_buf+(size_t)pix*C_);
  float4 v[4];
#pragma unroll
  for(int c4=0;c4<4;c4++){
    float4 t=s[c4];
    t.x*=am; t.y*=am; t.z*=am; t.w*=am;
    v[c4]=t;
  }
  float4* d=(float4*)(g_state_buf[nsel]+(size_t)pix*C_);
  d[0]=v[0];d[1]=v[1];d[2]=v[2];d[3]=v[3];
  write_frame(f,pix,v,stkF,rgbF,rgbU);
}

extern "C" void kernel_launch(void* const* d_in, const int* in_sizes, int n_in,
                              void* d_out, int out_size) {
  const float* st0=(const float*)d_in[0];
  const float* W1 =(const float*)d_in[1];
  const float* b1 =(const float*)d_in[2];
  const float* W2 =(const float*)d_in[3];
  const int*   um =(const int*)d_in[4];

  const long long SZ_RGB=33LL*NPIX_*3;     /* 20,275,200  */
  const long long SZ_STK=33LL*NPIX_*16;    /* 108,134,400 */

  float* stkF=0; float* rgbF=0; unsigned char* rgbU=0;
  long long osz=(long long)out_size;
  if(osz==SZ_RGB+SZ_STK){               /* float concat: rgb-as-float, then stacked */
    rgbF=(float*)d_out; stkF=(float*)d_out+SZ_RGB;
  }else if(osz==SZ_STK){                /* stacked only */
    stkF=(float*)d_out;
  }else if(osz==SZ_RGB){                /* rgb u8 only */
    rgbU=(unsigned char*)d_out;
  }else{                                /* byte concat: rgb u8, then stacked bytes */
    rgbU=(unsigned char*)d_out;
    stkF=(float*)((char*)d_out+SZ_RGB);
  }

  const int TB=256, NB=(NPIX_+TB-1)/TB;
  k_init<<<NB,TB>>>(st0,stkF,rgbF,rgbU);
  int sel=0;
  for(int t=0;t<32;t++){
    k_pre<<<dim3(5,5,B_),128>>>(sel,W1,b1,W2,um+(size_t)t*NPIX_);
    k_post<<<NB,TB>>>(sel^1,t+1,stkF,rgbF,rgbU);
    sel^=1;
  }
}

// round 4
// speedup vs baseline: 1.0140x; 1.0140x over previous
#include <cuda_runtime.h>

#define B_ 128
#define H_ 40
#define W_ 40
#define C_ 16
#define NPIX_ (B_*H_*W_)   /* 204800 */

/* Scratch (no allocations allowed): ping-pong state + pre-mask buffer. */
__device__ float g_state_buf[2][(size_t)NPIX_*C_];
__device__ float g_pre_buf[(size_t)NPIX_*C_];

typedef unsigned long long u64;

static __device__ __forceinline__ u64 pk2(float x){u64 r;asm("mov.b64 %0,{%1,%1};":"=l"(r):"f"(x));return r;}
static __device__ __forceinline__ void upk(u64 v,float&a,float&b){float x,y;asm("mov.b64 {%0,%1},%2;":"=f"(x),"=f"(y):"l"(v));a=x;b=y;}
static __device__ __forceinline__ u64 ffma2(u64 a,u64 b,u64 c){u64 d;asm("fma.rn.f32x2 %0,%1,%2,%3;":"=l"(d):"l"(a),"l"(b),"l"(c));return d;}
static __device__ __forceinline__ u64 fadd2(u64 a,u64 b){u64 d;asm("add.rn.f32x2 %0,%1,%2;":"=l"(d):"l"(a),"l"(b));return d;}

/* stacked frame + rgb writer for one pixel */
static __device__ __forceinline__ void write_frame(int f,int pix,const float4* v,
    float* stkF,float* rgbF,unsigned char* rgbU){
  size_t base=(size_t)f*NPIX_+pix;
  if(stkF){ float4* d=(float4*)(stkF+base*C_); d[0]=v[0];d[1]=v[1];d[2]=v[2];d[3]=v[3]; }
  if(rgbU||rgbF){
    float a=fminf(fmaxf(v[0].w,0.f),1.f);
    unsigned char r=(unsigned char)(fminf(fmaxf(1.f-a+v[0].x,0.f),1.f)*255.f);
    unsigned char g=(unsigned char)(fminf(fmaxf(1.f-a+v[0].y,0.f),1.f)*255.f);
    unsigned char b=(unsigned char)(fminf(fmaxf(1.f-a+v[0].z,0.f),1.f)*255.f);
    if(rgbU){ rgbU[base*3+0]=r; rgbU[base*3+1]=g; rgbU[base*3+2]=b; }
    if(rgbF){ rgbF[base*3+0]=(float)r; rgbF[base*3+1]=(float)g; rgbF[base*3+2]=(float)b; }
  }
}

/* ---- init: state[0] = input; emit frame 0 ---- */
__global__ void k_init(const float* __restrict__ st0,
                       float* stkF,float* rgbF,unsigned char* rgbU){
  int pix=blockIdx.x*blockDim.x+threadIdx.x;
  if(pix>=NPIX_) return;
  float4 v[4];
  const float4* s=(const float4*)(st0+(size_t)pix*C_);
  v[0]=s[0];v[1]=s[1];v[2]=s[2];v[3]=s[3];
  float4* d=(float4*)(g_state_buf[0]+(size_t)pix*C_);
  d[0]=v[0];d[1]=v[1];d[2]=v[2];d[3]=v[3];
  write_frame(0,pix,v,stkF,rgbF,rgbU);
}

/* ---- K1: pre = state + mask*MLP(perception(alive-masked state)) ----
 * grid (5,5,128) of 8x8 tiles; 128 thr = 16 pixel-quads x 8 hidden-groups.
 * Each thread: 4 pixels x 16 hidden (GEMM1) and 4 px x 16 outs partial (GEMM2). */
__global__ void __launch_bounds__(128) k_pre(int sel,
    const float* __restrict__ W1,const float* __restrict__ b1,
    const float* __restrict__ W2,const int* __restrict__ umask)
{
  /* weight layouts: conflict-free banked chunks [..][ci][jg][4floats] */
  __shared__ __align__(16) float sW1[48*4*8*4];    /* 24576 B */
  __shared__ __align__(16) float sW2[8*2*4*8*4];   /*  8192 B */
  __shared__ __align__(16) float sP[48*64];        /* 12288 B ; first 144 floats reused as alpha halo */
  __shared__ float sM[8*110];                      /*  3520 B ; 8 ch x 10y x pitch11 */
  __shared__ float sAm[100];

  const int tid=threadIdx.x;
  const int b=blockIdx.z, by0=blockIdx.y*8, bx0=blockIdx.x*8;
  const float* __restrict__ sb=g_state_buf[sel]+(size_t)b*H_*W_*C_;

  /* stage W1: global [j(128)][i(48)] -> sW1[i][l>>2][jg][l&3] */
  for(int idx=tid; idx<6144; idx+=128){
    int j=idx/48, i=idx-j*48;
    int jg=j>>4, l=j&15;
    sW1[(((i<<2)+(l>>2))<<5) + (jg<<2) + (l&3)] = W1[idx];
  }
  /* stage W2: global [o(16)][j(128)] -> sW2[hp][lh][o>>2][jg][o&3] */
  for(int idx=tid; idx<2048; idx+=128){
    int o=idx>>7, j=idx&127;
    int jg=j>>4, l=j&15, hp=l>>1, lh=l&1;
    sW2[((((hp*2+lh)<<2)+(o>>2))<<5) + (jg<<2) + (o&3)] = W2[idx];
  }
  /* alpha with halo 2 into sP[0..143] (OOB=-inf) */
  for(int idx=tid; idx<144; idx+=128){
    int ay=idx/12, ax=idx-ay*12;
    int gy=by0-2+ay, gx=bx0-2+ax;
    float a=-1e30f;
    if((unsigned)gy<(unsigned)H_ && (unsigned)gx<(unsigned)W_) a=sb[(gy*W_+gx)*C_+3];
    sP[idx]=a;
  }
  __syncthreads();

  /* alive mask on 10x10 (halo 1) */
  for(int idx=tid; idx<100; idx+=128){
    int my=idx/10, mx=idx-my*10;
    const float* a0=&sP[my*12+mx];
    float m=a0[0]; m=fmaxf(m,a0[1]); m=fmaxf(m,a0[2]);
    m=fmaxf(m,a0[12]); m=fmaxf(m,a0[13]); m=fmaxf(m,a0[14]);
    m=fmaxf(m,a0[24]); m=fmaxf(m,a0[25]); m=fmaxf(m,a0[26]);
    sAm[idx]=(m>=0.1f)?1.0f:0.0f;
  }
  __syncthreads();

  /* build perception sP[48][64] in two 8-channel halves through sM */
  for(int h=0;h<2;h++){
    for(int idx=tid; idx<200; idx+=128){
      int p2=idx>>1, c4h=idx&1;
      int my=p2/10, mx=p2-my*10;
      int gy=by0-1+my, gx=bx0-1+mx;
      float4 v=make_float4(0.f,0.f,0.f,0.f);
      if((unsigned)gy<(unsigned)H_ && (unsigned)gx<(unsigned)W_)
        v=*(const float4*)&sb[(gy*W_+gx)*C_ + h*8 + c4h*4];
      float am=sAm[p2];
      int cc0=c4h*4, rb=my*11+mx;
      sM[(cc0  )*110+rb]=v.x*am;
      sM[(cc0+1)*110+rb]=v.y*am;
      sM[(cc0+2)*110+rb]=v.z*am;
      sM[(cc0+3)*110+rb]=v.w*am;
    }
    __syncthreads();
    for(int idx=tid; idx<512; idx+=128){
      int cc=idx>>6, p=idx&63;
      int py=p>>3, px=p&7;
      const float* m=&sM[cc*110 + py*11 + px];
      float m00=m[0],  m01=m[1],  m02=m[2];
      float m10=m[11], m11=m[12], m12=m[13];
      float m20=m[22], m21=m[23], m22=m[24];
      int cg=h*8+cc;
      sP[cg*64+p]      = m11;
      sP[(16+cg)*64+p] = ((m02+2.f*m12+m22)-(m00+2.f*m10+m20))*0.125f;
      sP[(32+cg)*64+p] = ((m20+2.f*m21+m22)-(m00+2.f*m01+m02))*0.125f;
    }
    __syncthreads();
  }

  const int jg=tid&7, pp=tid>>3;   /* pixel base p = pp*4 */

  /* acc[hp][px]: hidden pair (2hp,2hp+1) packed in f32x2, init = bias */
  u64 acc[8][4];
  {
    const ulonglong2* bp=(const ulonglong2*)(b1 + jg*16);
#pragma unroll
    for(int c=0;c<4;c++){
      ulonglong2 q=bp[c];
#pragma unroll
      for(int p=0;p<4;p++){ acc[2*c][p]=q.x; acc[2*c+1][p]=q.y; }
    }
  }

  const ulonglong2* sW1v=(const ulonglong2*)sW1;
  const ulonglong2* sW2v=(const ulonglong2*)sW2;

  /* GEMM1: 48 perception comps -> 16 hidden for 4 px */
#pragma unroll 4
  for(int i=0;i<48;i++){
    float4 pv=*(const float4*)&sP[i*64 + pp*4];
    u64 pd0=pk2(pv.x), pd1=pk2(pv.y), pd2=pk2(pv.z), pd3=pk2(pv.w);
#pragma unroll
    for(int ci=0;ci<4;ci++){
      ulonglong2 w=sW1v[(i*4+ci)*8 + jg];
      acc[2*ci  ][0]=ffma2(w.x,pd0,acc[2*ci  ][0]);
      acc[2*ci  ][1]=ffma2(w.x,pd1,acc[2*ci  ][1]);
      acc[2*ci  ][2]=ffma2(w.x,pd2,acc[2*ci  ][2]);
      acc[2*ci  ][3]=ffma2(w.x,pd3,acc[2*ci  ][3]);
      acc[2*ci+1][0]=ffma2(w.y,pd0,acc[2*ci+1][0]);
      acc[2*ci+1][1]=ffma2(w.y,pd1,acc[2*ci+1][1]);
      acc[2*ci+1][2]=ffma2(w.y,pd2,acc[2*ci+1][2]);
      acc[2*ci+1][3]=ffma2(w.y,pd3,acc[2*ci+1][3]);
    }
  }

  /* ReLU + GEMM2: 16 hidden -> 16 outputs (out pairs packed) for 4 px */
  u64 u[8][4];
#pragma unroll
  for(int k=0;k<8;k++){u[k][0]=0ull;u[k][1]=0ull;u[k][2]=0ull;u[k][3]=0ull;}
#pragma unroll
  for(int hp=0;hp<8;hp++){
    u64 hv0[4],hv1[4];
#pragma unroll
    for(int p=0;p<4;p++){
      float a,bv; upk(acc[hp][p],a,bv);
      hv0[p]=pk2(fmaxf(a,0.f));
      hv1[p]=pk2(fmaxf(bv,0.f));
    }
#pragma unroll
    for(int ci=0;ci<4;ci++){
      ulonglong2 w=sW2v[((hp*2+0)*4+ci)*8 + jg];
      u[2*ci  ][0]=ffma2(w.x,hv0[0],u[2*ci  ][0]);
      u[2*ci  ][1]=ffma2(w.x,hv0[1],u[2*ci  ][1]);
      u[2*ci  ][2]=ffma2(w.x,hv0[2],u[2*ci  ][2]);
      u[2*ci  ][3]=ffma2(w.x,hv0[3],u[2*ci  ][3]);
      u[2*ci+1][0]=ffma2(w.y,hv0[0],u[2*ci+1][0]);
      u[2*ci+1][1]=ffma2(w.y,hv0[1],u[2*ci+1][1]);
      u[2*ci+1][2]=ffma2(w.y,hv0[2],u[2*ci+1][2]);
      u[2*ci+1][3]=ffma2(w.y,hv0[3],u[2*ci+1][3]);
    }
#pragma unroll
    for(int ci=0;ci<4;ci++){
      ulonglong2 w=sW2v[((hp*2+1)*4+ci)*8 + jg];
      u[2*ci  ][0]=ffma2(w.x,hv1[0],u[2*ci  ][0]);
      u[2*ci  ][1]=ffma2(w.x,hv1[1],u[2*ci  ][1]);
      u[2*ci  ][2]=ffma2(w.x,hv1[2],u[2*ci  ][2]);
      u[2*ci  ][3]=ffma2(w.x,hv1[3],u[2*ci  ][3]);
      u[2*ci+1][0]=ffma2(w.y,hv1[0],u[2*ci+1][0]);
      u[2*ci+1][1]=ffma2(w.y,hv1[1],u[2*ci+1][1]);
      u[2*ci+1][2]=ffma2(w.y,hv1[2],u[2*ci+1][2]);
      u[2*ci+1][3]=ffma2(w.y,hv1[3],u[2*ci+1][3]);
    }
  }

  /* reduce over 8 hidden-groups (lane bits 0..2) */
#pragma unroll
  for(int k=0;k<8;k++){
#pragma unroll
    for(int p=0;p<4;p++){
      u[k][p]=fadd2(u[k][p], __shfl_xor_sync(0xffffffffu,u[k][p],1));
      u[k][p]=fadd2(u[k][p], __shfl_xor_sync(0xffffffffu,u[k][p],2));
      u[k][p]=fadd2(u[k][p], __shfl_xor_sync(0xffffffffu,u[k][p],4));
    }
  }

  if(jg==0){
    int py=pp>>1, px0=(pp&1)*4;
    int gy=by0+py, gx0=bx0+px0;
    int4 m4=*(const int4*)&umask[(b*H_+gy)*W_+gx0];
    int mv[4]; mv[0]=m4.x; mv[1]=m4.y; mv[2]=m4.z; mv[3]=m4.w;
#pragma unroll
    for(int p=0;p<4;p++){
      float o_[16];
#pragma unroll
      for(int op=0;op<8;op++) upk(u[op][p], o_[2*op], o_[2*op+1]);
      float mf=(float)mv[p];
      const float4* s=(const float4*)&sb[(gy*W_+gx0+p)*C_];
      float4* d=(float4*)(g_pre_buf+((size_t)(b*H_+gy)*W_+gx0+p)*C_);
#pragma unroll
      for(int c4=0;c4<4;c4++){
        float4 a=s[c4];
        a.x+=mf*o_[4*c4+0]; a.y+=mf*o_[4*c4+1];
        a.z+=mf*o_[4*c4+2]; a.w+=mf*o_[4*c4+3];
        d[c4]=a;
      }
    }
  }
}

/* ---- K2: new = pre * alive_mask(pre); store state + frame ---- */
__global__ void k_post(int nsel,int f,float* stkF,float* rgbF,unsigned char* rgbU){
  int pix=blockIdx.x*blockDim.x+threadIdx.x;
  if(pix>=NPIX_) return;
  int b=pix/(H_*W_); int rem=pix-b*(H_*W_); int y=rem/W_; int x=rem-y*W_;
  float m=-1e30f;
#pragma unroll
  for(int dy=-1;dy<=1;dy++){
    int yy=y+dy; if((unsigned)yy>=(unsigned)H_) continue;
#pragma unroll
    for(int dx=-1;dx<=1;dx++){
      int xx=x+dx; if((unsigned)xx>=(unsigned)W_) continue;
      m=fmaxf(m, g_pre_buf[((size_t)(b*H_+yy)*W_+xx)*C_+3]);
    }
  }
  float am=(m>=0.1f)?1.0f:0.0f;
  const float4* s=(const float4*)(g_pre_buf+(size_t)pix*C_);
  float4 v[4];
#pragma unroll
  for(int c4=0;c4<4;c4++){
    float4 t=s[c4];
    t.x*=am; t.y*=am; t.z*=am; t.w*=am;
    v[c4]=t;
  }
  float4* d=(float4*)(g_state_buf[nsel]+(size_t)pix*C_);
  d[0]=v[0];d[1]=v[1];d[2]=v[2];d[3]=v[3];
  write_frame(f,pix,v,stkF,rgbF,rgbU);
}

extern "C" void kernel_launch(void* const* d_in, const int* in_sizes, int n_in,
                              void* d_out, int out_size) {
  const float* st0=(const float*)d_in[0];
  const float* W1 =(const float*)d_in[1];
  const float* b1 =(const float*)d_in[2];
  const float* W2 =(const float*)d_in[3];
  const int*   um =(const int*)d_in[4];

  const long long SZ_RGB=33LL*NPIX_*3;     /* 20,275,200  */
  const long long SZ_STK=33LL*NPIX_*16;    /* 108,134,400 */

  float* stkF=0; float* rgbF=0; unsigned char* rgbU=0;
  long long osz=(long long)out_size;
  if(osz==SZ_RGB+SZ_STK){               /* float concat: rgb-as-float, then stacked */
    rgbF=(float*)d_out; stkF=(float*)d_out+SZ_RGB;
  }else if(osz==SZ_STK){                /* stacked only */
    stkF=(float*)d_out;
  }else if(osz==SZ_RGB){                /* rgb u8 only */
    rgbU=(unsigned char*)d_out;
  }else{                                /* byte concat: rgb u8, then stacked bytes */
    rgbU=(unsigned char*)d_out;
    stkF=(float*)((char*)d_out+SZ_RGB);
  }

  const int TB=256, NB=(NPIX_+TB-1)/TB;
  k_init<<<NB,TB>>>(st0,stkF,rgbF,rgbU);
  int sel=0;
  for(int t=0;t<32;t++){
    k_pre<<<dim3(5,5,B_),128>>>(sel,W1,b1,W2,um+(size_t)t*NPIX_);
    k_post<<<NB,TB>>>(sel^1,t+1,stkF,rgbF,rgbU);
    sel^=1;
  }
}